// round 10
// baseline (speedup 1.0000x reference)
#include <cuda_runtime.h>

#define CDIV(a,b) (((a)+(b)-1)/(b))

static const int MAXN = 100000;
static const int MAXE = 1600000;
static const int BK   = 64;      // bucket capacity; P(deg>64) ~ 1e-18

// ---------------- scratch (device globals; no allocation) ----------------
__device__ int g_cnt[MAXN];
__device__ int g_buck[MAXN * BK];

__device__ __align__(16) float g_y1[MAXN*32];
__device__ __align__(16) float g_z1[MAXN*32];
__device__ __align__(16) float g_y2[MAXN*48];
__device__ __align__(16) float g_z2[MAXN*48];
__device__ __align__(16) float g_y3[MAXN*16];
__device__ __align__(16) float g_z3[MAXN*16];

// ---------------- bucket build (scan-free CSR) ----------------
__global__ void zero_cnt_kernel(int N) {
    int t = blockIdx.x * blockDim.x + threadIdx.x;
    if (t < N) g_cnt[t] = 0;
}

__global__ void bucket_kernel(const int* __restrict__ ei, int E, int N) {
    int t = blockIdx.x * blockDim.x + threadIdx.x;
    if (t >= E) return;
    int s = min(max(ei[t], 0), N - 1);
    int d = min(max(ei[E + t], 0), N - 1);
    int p = atomicAdd(&g_cnt[d], 1);
    if (p < BK) g_buck[d * BK + p] = s;
}

// ---------------- layer 1 GEMM: y1 = h@W1rel, z1 = h@W1root + b1 --------
__global__ void __launch_bounds__(256) gemm1_kernel(
    const float* __restrict__ x, const float* __restrict__ ax,
    const float* __restrict__ Wr, const float* __restrict__ Wo,
    const float* __restrict__ bias, int N)
{
    constexpr int IN = 64, OUT = 32, O8 = OUT / 8;
    __shared__ float sWr[IN * OUT];
    __shared__ float sWz[IN * OUT];
    __shared__ float sB[OUT];
    int tid = threadIdx.x;
    for (int i = tid; i < IN * OUT; i += 256) {
        sWr[i] = Wr[i];
        sWz[i] = Wo[i];
    }
    if (tid < OUT) sB[tid] = bias[tid];
    __syncthreads();

    int n  = blockIdx.x * 128 + (tid & 127);
    int og = tid >> 7;
    if (n >= N) return;

    float h[IN];
#pragma unroll
    for (int c = 0; c < 12; c++) {
        float4 v = __ldg((const float4*)x + n * 12 + c);
        h[4*c+0] = v.x; h[4*c+1] = v.y; h[4*c+2] = v.z; h[4*c+3] = v.w;
    }
#pragma unroll
    for (int c = 0; c < 4; c++) {
        float4 v = __ldg((const float4*)ax + n * 4 + c);
        h[48+4*c+0] = v.x; h[48+4*c+1] = v.y;
        h[48+4*c+2] = v.z; h[48+4*c+3] = v.w;
    }

#pragma unroll
    for (int oo = 0; oo < O8; oo++) {
        int o4 = og * O8 + oo;
        float4 ar = make_float4(0.f, 0.f, 0.f, 0.f);
        float4 az = *(const float4*)&sB[o4 * 4];
#pragma unroll
        for (int k = 0; k < IN; k++) {
            float4 wr = *(const float4*)&sWr[k * OUT + o4 * 4];
            float4 wz = *(const float4*)&sWz[k * OUT + o4 * 4];
            ar.x = fmaf(h[k], wr.x, ar.x);
            ar.y = fmaf(h[k], wr.y, ar.y);
            ar.z = fmaf(h[k], wr.z, ar.z);
            ar.w = fmaf(h[k], wr.w, ar.w);
            az.x = fmaf(h[k], wz.x, az.x);
            az.y = fmaf(h[k], wz.y, az.y);
            az.z = fmaf(h[k], wz.z, az.z);
            az.w = fmaf(h[k], wz.w, az.w);
        }
        ((float4*)g_y1)[n * (OUT/4) + o4] = ar;
        ((float4*)g_z1)[n * (OUT/4) + o4] = az;
    }
}

// ---------------- fused layer: gather + relu + dual GEMM -----------------
// 4 threads per node (TPN=4), block = 256 = 64 nodes.
// Gather: per LDG a warp touches 8 node rows. Handoff via padded smem h
// tile with __syncwarp only (the 4 subs of a node share a warp). GEMM is
// k-outer reading h from smem (broadcast LDS.32); accumulators are the
// only live state. __launch_bounds__(256,5) pins ~62% occupancy.
template<int INA, int INB, int OUT>
__device__ __forceinline__ void fused_layer(
    const float* __restrict__ yprev, const float* __restrict__ zprev,
    const float* __restrict__ B,
    const float* __restrict__ Wr, const float* __restrict__ Wo,
    const float* __restrict__ bias,
    float* __restrict__ y, float* __restrict__ z, int N)
{
    constexpr int TPN = 4;
    constexpr int NPB = 256 / TPN;          // 64 nodes per block
    constexpr int IN  = INA + INB;
    constexpr int A4  = INA / 4;            // gathered float4 chunks
    constexpr int CPT = A4 / TPN;           // chunks per sub-thread
    constexpr int B4  = INB / 4;            // extra-input chunks
    constexpr int O4  = OUT / 4;
    constexpr int OPT = O4 / TPN;           // output float4s per sub-thread
    constexpr int SH  = IN + 4;             // padded row stride (floats)

    __shared__ float sWr[IN * OUT];
    __shared__ float sWz[IN * OUT];
    __shared__ float sB[OUT];
    __shared__ __align__(16) float sH[NPB * SH];

    int tid = threadIdx.x;
    for (int i = tid; i < IN * OUT; i += 256) {
        sWr[i] = Wr[i];
        sWz[i] = Wo[i];
    }
    if (tid < OUT) sB[tid] = bias[tid];
    __syncthreads();   // weights visible to all warps before GEMM phase

    int nl  = tid / TPN;
    int sub = tid % TPN;
    int n   = blockIdx.x * NPB + nl;
    bool valid = (n < N);

    if (valid) {
        float4 acc[CPT];
#pragma unroll
        for (int c = 0; c < CPT; c++) acc[c] = make_float4(0.f, 0.f, 0.f, 0.f);

        int cnt = min(g_cnt[n], BK);
        const int* bk = &g_buck[n * BK];
        const float4* yp = (const float4*)yprev;
        for (int j = 0; j < cnt; j++) {
            int s = __ldg(bk + j);
#pragma unroll
            for (int c = 0; c < CPT; c++) {
                float4 v = __ldg(yp + (long)s * A4 + sub * CPT + c);
                acc[c].x += v.x; acc[c].y += v.y;
                acc[c].z += v.z; acc[c].w += v.w;
            }
        }
        // relu(acc + z) -> smem h tile
#pragma unroll
        for (int c = 0; c < CPT; c++) {
            int ch = sub * CPT + c;
            float4 zz = ((const float4*)zprev)[n * A4 + ch];
            float* hp = &sH[nl * SH + ch * 4];
            hp[0] = fmaxf(acc[c].x + zz.x, 0.f);
            hp[1] = fmaxf(acc[c].y + zz.y, 0.f);
            hp[2] = fmaxf(acc[c].z + zz.z, 0.f);
            hp[3] = fmaxf(acc[c].w + zz.w, 0.f);
        }
        if constexpr (B4 > 0) {
            static_assert(B4 == TPN || B4 == 0, "B4 must equal TPN");
            float4 v = __ldg((const float4*)B + n * B4 + sub);
            float* hp = &sH[nl * SH + (A4 + sub) * 4];
            hp[0] = v.x; hp[1] = v.y; hp[2] = v.z; hp[3] = v.w;
        }
    }
    __syncwarp();      // producers and consumers of sH share the warp

    if (!valid) return;

    // k-outer dual GEMM: h stays in smem (broadcast LDS.32 per k).
    float4 aR[OPT], aZ[OPT];
#pragma unroll
    for (int oo = 0; oo < OPT; oo++) {
        aR[oo] = make_float4(0.f, 0.f, 0.f, 0.f);
        aZ[oo] = *(const float4*)&sB[(sub * OPT + oo) * 4];
    }
    const float* hrow = &sH[nl * SH];
#pragma unroll
    for (int k = 0; k < IN; k++) {
        float hk = hrow[k];
#pragma unroll
        for (int oo = 0; oo < OPT; oo++) {
            int o4 = sub * OPT + oo;
            float4 wr = *(const float4*)&sWr[k * OUT + o4 * 4];
            float4 wz = *(const float4*)&sWz[k * OUT + o4 * 4];
            aR[oo].x = fmaf(hk, wr.x, aR[oo].x);
            aR[oo].y = fmaf(hk, wr.y, aR[oo].y);
            aR[oo].z = fmaf(hk, wr.z, aR[oo].z);
            aR[oo].w = fmaf(hk, wr.w, aR[oo].w);
            aZ[oo].x = fmaf(hk, wz.x, aZ[oo].x);
            aZ[oo].y = fmaf(hk, wz.y, aZ[oo].y);
            aZ[oo].z = fmaf(hk, wz.z, aZ[oo].z);
            aZ[oo].w = fmaf(hk, wz.w, aZ[oo].w);
        }
    }
#pragma unroll
    for (int oo = 0; oo < OPT; oo++) {
        int o4 = sub * OPT + oo;
        ((float4*)y)[n * O4 + o4] = aR[oo];
        ((float4*)z)[n * O4 + o4] = aZ[oo];
    }
}

__global__ void __launch_bounds__(256, 5) fused2_kernel(
    const float* __restrict__ lf,
    const float* __restrict__ Wr, const float* __restrict__ Wo,
    const float* __restrict__ b, int N)
{
    fused_layer<32, 16, 48>(g_y1, g_z1, lf, Wr, Wo, b, g_y2, g_z2, N);
}

__global__ void __launch_bounds__(256, 5) fused3_kernel(
    const float* __restrict__ Wr, const float* __restrict__ Wo,
    const float* __restrict__ b, int N)
{
    fused_layer<48, 0, 16>(g_y2, g_z2, nullptr, Wr, Wo, b, g_y3, g_z3, N);
}

// ---------------- final gather + epilogue: out = sum y3[src] + z3 + ax ---
__global__ void gather_final_kernel(const float* __restrict__ ax,
                                    float* __restrict__ out, int N)
{
    int t = blockIdx.x * blockDim.x + threadIdx.x;
    if (t >= N * 4) return;
    int n = t >> 2;
    int c = t & 3;
    int cnt = min(g_cnt[n], BK);
    const int* bk = &g_buck[n * BK];
    float4 acc = make_float4(0.f, 0.f, 0.f, 0.f);
    int j = 0;
    for (; j + 4 <= cnt; j += 4) {
        int s0 = __ldg(bk+j+0), s1 = __ldg(bk+j+1);
        int s2 = __ldg(bk+j+2), s3 = __ldg(bk+j+3);
        float4 v0 = __ldg((const float4*)g_y3 + (long)s0 * 4 + c);
        float4 v1 = __ldg((const float4*)g_y3 + (long)s1 * 4 + c);
        float4 v2 = __ldg((const float4*)g_y3 + (long)s2 * 4 + c);
        float4 v3 = __ldg((const float4*)g_y3 + (long)s3 * 4 + c);
        acc.x += (v0.x + v1.x) + (v2.x + v3.x);
        acc.y += (v0.y + v1.y) + (v2.y + v3.y);
        acc.z += (v0.z + v1.z) + (v2.z + v3.z);
        acc.w += (v0.w + v1.w) + (v2.w + v3.w);
    }
    for (; j < cnt; j++) {
        int s = __ldg(bk + j);
        float4 v = __ldg((const float4*)g_y3 + (long)s * 4 + c);
        acc.x += v.x; acc.y += v.y; acc.z += v.z; acc.w += v.w;
    }
    float4 zz = ((const float4*)g_z3)[t];
    float4 xx = __ldg((const float4*)ax + t);
    ((float4*)out)[t] = make_float4(acc.x + zz.x + xx.x,
                                    acc.y + zz.y + xx.y,
                                    acc.z + zz.z + xx.z,
                                    acc.w + zz.w + xx.w);
}

// ---------------- launch ----------------
// Fork-join: bucket build (LTS-atomic-bound) runs on a side stream in
// parallel with gemm1 (FMA-bound). Stream/events are created once on the
// first (uncaptured correctness) call; under capture the event edges
// become parallel graph branches. Work is identical on every call.
extern "C" void kernel_launch(void* const* d_in, const int* in_sizes, int n_in,
                              void* d_out, int out_size)
{
    (void)n_in; (void)out_size;
    const float* x   = (const float*)d_in[0];
    const int*   ei  = (const int*)d_in[1];     // int32 (JAX x64 disabled)
    const float* ax  = (const float*)d_in[2];
    const float* lf  = (const float*)d_in[3];
    const float* W1r = (const float*)d_in[4];
    const float* b1  = (const float*)d_in[5];
    const float* W1o = (const float*)d_in[6];
    const float* W2r = (const float*)d_in[7];
    const float* b2  = (const float*)d_in[8];
    const float* W2o = (const float*)d_in[9];
    const float* W3r = (const float*)d_in[10];
    const float* b3  = (const float*)d_in[11];
    const float* W3o = (const float*)d_in[12];

    int N = in_sizes[0] / 48;
    int E = in_sizes[1] / 2;

    static cudaStream_t side = nullptr;
    static cudaEvent_t ev_fork = nullptr, ev_join = nullptr;
    if (!side) {
        cudaStreamCreateWithFlags(&side, cudaStreamNonBlocking);
        cudaEventCreateWithFlags(&ev_fork, cudaEventDisableTiming);
        cudaEventCreateWithFlags(&ev_join, cudaEventDisableTiming);
    }

    // fork: side stream inherits ordering from the main stream
    cudaEventRecord(ev_fork, 0);
    cudaStreamWaitEvent(side, ev_fork, 0);

    // side branch: bucket build
    zero_cnt_kernel<<<CDIV(N, 256), 256, 0, side>>>(N);
    bucket_kernel<<<CDIV(E, 256), 256, 0, side>>>(ei, E, N);
    cudaEventRecord(ev_join, side);

    // main branch: layer-1 GEMM (independent of buckets)
    gemm1_kernel<<<CDIV(N, 128), 256>>>(x, ax, W1r, W1o, b1, N);

    // join: everything after needs both branches
    cudaStreamWaitEvent(0, ev_join, 0);

    fused2_kernel<<<CDIV(N, 64), 256>>>(lf, W2r, W2o, b2, N);
    fused3_kernel<<<CDIV(N, 64), 256>>>(W3r, W3o, b3, N);
    gather_final_kernel<<<CDIV(N * 4, 256), 256>>>(ax, (float*)d_out, N);
}

// round 11
// speedup vs baseline: 1.2007x; 1.2007x over previous
#include <cuda_runtime.h>

#define CDIV(a,b) (((a)+(b)-1)/(b))

static const int MAXN = 100000;
static const int MAXE = 1600000;
static const int BK   = 64;      // bucket capacity; P(deg>64) ~ 1e-18

// ---------------- scratch (device globals; no allocation) ----------------
__device__ int g_cnt[MAXN];
__device__ int g_buck[MAXN * BK];

__device__ __align__(16) float g_y1[MAXN*32];
__device__ __align__(16) float g_z1[MAXN*32];
__device__ __align__(16) float g_y2[MAXN*48];
__device__ __align__(16) float g_z2[MAXN*48];
__device__ __align__(16) float g_y3[MAXN*16];
__device__ __align__(16) float g_z3[MAXN*16];

// ---------------- bucket build (scan-free CSR) ----------------
__global__ void zero_cnt_kernel(int N) {
    int t = blockIdx.x * blockDim.x + threadIdx.x;
    if (t < N) g_cnt[t] = 0;
}

__global__ void bucket_kernel(const int* __restrict__ ei, int E, int N) {
    int t = blockIdx.x * blockDim.x + threadIdx.x;
    if (t >= E) return;
    int s = min(max(ei[t], 0), N - 1);
    int d = min(max(ei[E + t], 0), N - 1);
    int p = atomicAdd(&g_cnt[d], 1);
    if (p < BK) g_buck[d * BK + p] = s;
}

// ---------------- layer 1 GEMM: y1 = h@W1rel, z1 = h@W1root + b1 --------
__global__ void __launch_bounds__(256) gemm1_kernel(
    const float* __restrict__ x, const float* __restrict__ ax,
    const float* __restrict__ Wr, const float* __restrict__ Wo,
    const float* __restrict__ bias, int N)
{
    constexpr int IN = 64, OUT = 32, O8 = OUT / 8;
    __shared__ float sWr[IN * OUT];
    __shared__ float sWz[IN * OUT];
    __shared__ float sB[OUT];
    int tid = threadIdx.x;
    for (int i = tid; i < IN * OUT; i += 256) {
        sWr[i] = Wr[i];
        sWz[i] = Wo[i];
    }
    if (tid < OUT) sB[tid] = bias[tid];
    __syncthreads();

    int n  = blockIdx.x * 128 + (tid & 127);
    int og = tid >> 7;
    if (n >= N) return;

    float h[IN];
#pragma unroll
    for (int c = 0; c < 12; c++) {
        float4 v = __ldg((const float4*)x + n * 12 + c);
        h[4*c+0] = v.x; h[4*c+1] = v.y; h[4*c+2] = v.z; h[4*c+3] = v.w;
    }
#pragma unroll
    for (int c = 0; c < 4; c++) {
        float4 v = __ldg((const float4*)ax + n * 4 + c);
        h[48+4*c+0] = v.x; h[48+4*c+1] = v.y;
        h[48+4*c+2] = v.z; h[48+4*c+3] = v.w;
    }

#pragma unroll
    for (int oo = 0; oo < O8; oo++) {
        int o4 = og * O8 + oo;
        float4 ar = make_float4(0.f, 0.f, 0.f, 0.f);
        float4 az = *(const float4*)&sB[o4 * 4];
#pragma unroll
        for (int k = 0; k < IN; k++) {
            float4 wr = *(const float4*)&sWr[k * OUT + o4 * 4];
            float4 wz = *(const float4*)&sWz[k * OUT + o4 * 4];
            ar.x = fmaf(h[k], wr.x, ar.x);
            ar.y = fmaf(h[k], wr.y, ar.y);
            ar.z = fmaf(h[k], wr.z, ar.z);
            ar.w = fmaf(h[k], wr.w, ar.w);
            az.x = fmaf(h[k], wz.x, az.x);
            az.y = fmaf(h[k], wz.y, az.y);
            az.z = fmaf(h[k], wz.z, az.z);
            az.w = fmaf(h[k], wz.w, az.w);
        }
        ((float4*)g_y1)[n * (OUT/4) + o4] = ar;
        ((float4*)g_z1)[n * (OUT/4) + o4] = az;
    }
}

// ---------------- fused layer: gather + relu + dual node-blocked GEMM ----
// Phase 1 (256 threads, 4/node): gather rows, relu(+z), write TRANSPOSED
//   h tile sHT[k][node] (row stride SP=68 -> aligned float4, no read
//   conflicts).
// Phase 2 (NG*O4 threads): thread = (node-group of NB, o4). Per k: one
//   float4 of h covers NB nodes, so each weight LDS.128 feeds NB x 8 FMAs
//   -> weight crossbar traffic / NB vs R10.
template<int INA, int INB, int OUT, int NB>
__device__ __forceinline__ void fused_layer(
    const float* __restrict__ yprev, const float* __restrict__ zprev,
    const float* __restrict__ B,
    const float* __restrict__ Wr, const float* __restrict__ Wo,
    const float* __restrict__ bias,
    float* __restrict__ y, float* __restrict__ z, int N)
{
    constexpr int TPN = 4;
    constexpr int NPB = 64;                 // nodes per block
    constexpr int IN  = INA + INB;
    constexpr int A4  = INA / 4;            // gathered float4 chunks
    constexpr int CPT = A4 / TPN;           // chunks per sub-thread
    constexpr int B4  = INB / 4;            // extra-input chunks
    constexpr int O4  = OUT / 4;
    constexpr int SP  = 68;                 // sHT row stride (floats), %4==0
    constexpr int NG  = NPB / NB;           // node groups
    constexpr int NT  = NG * O4;            // GEMM threads
    static_assert(NT <= 256, "GEMM thread count");

    __shared__ float sWr[IN * OUT];
    __shared__ float sWz[IN * OUT];
    __shared__ float sB[OUT];
    __shared__ __align__(16) float sHT[IN * SP];

    int tid = threadIdx.x;
    for (int i = tid; i < IN * OUT; i += 256) {
        sWr[i] = Wr[i];
        sWz[i] = Wo[i];
    }
    if (tid < OUT) sB[tid] = bias[tid];

    // ---- phase 1: gather ----
    int nl  = tid / TPN;
    int sub = tid % TPN;
    int n   = blockIdx.x * NPB + nl;

    if (n < N) {
        float4 acc[CPT];
#pragma unroll
        for (int c = 0; c < CPT; c++) acc[c] = make_float4(0.f, 0.f, 0.f, 0.f);

        int cnt = min(g_cnt[n], BK);
        const int* bk = &g_buck[n * BK];
        const float4* yp = (const float4*)yprev;
        for (int j = 0; j < cnt; j++) {
            int s = __ldg(bk + j);
#pragma unroll
            for (int c = 0; c < CPT; c++) {
                float4 v = __ldg(yp + (long)s * A4 + sub * CPT + c);
                acc[c].x += v.x; acc[c].y += v.y;
                acc[c].z += v.z; acc[c].w += v.w;
            }
        }
#pragma unroll
        for (int c = 0; c < CPT; c++) {
            int ch = sub * CPT + c;
            float4 zz = ((const float4*)zprev)[n * A4 + ch];
            int kb = ch * 4;
            sHT[(kb+0) * SP + nl] = fmaxf(acc[c].x + zz.x, 0.f);
            sHT[(kb+1) * SP + nl] = fmaxf(acc[c].y + zz.y, 0.f);
            sHT[(kb+2) * SP + nl] = fmaxf(acc[c].z + zz.z, 0.f);
            sHT[(kb+3) * SP + nl] = fmaxf(acc[c].w + zz.w, 0.f);
        }
        if constexpr (B4 > 0) {
            static_assert(B4 == TPN || B4 == 0, "B4 must equal TPN");
            float4 v = __ldg((const float4*)B + n * B4 + sub);
            int kb = INA + sub * 4;
            sHT[(kb+0) * SP + nl] = v.x;
            sHT[(kb+1) * SP + nl] = v.y;
            sHT[(kb+2) * SP + nl] = v.z;
            sHT[(kb+3) * SP + nl] = v.w;
        }
    }
    __syncthreads();

    // ---- phase 2: node-blocked dual GEMM ----
    if (tid >= NT) return;
    int o4 = tid % O4;
    int ng = tid / O4;
    int n0 = blockIdx.x * NPB + ng * NB;

    float4 aR[NB], aZ[NB];
    float4 bias4 = *(const float4*)&sB[o4 * 4];
#pragma unroll
    for (int i = 0; i < NB; i++) {
        aR[i] = make_float4(0.f, 0.f, 0.f, 0.f);
        aZ[i] = bias4;
    }

#pragma unroll
    for (int k = 0; k < IN; k++) {
        float hv[NB];
        if constexpr (NB == 4) {
            float4 t4 = *(const float4*)&sHT[k * SP + ng * 4];
            hv[0] = t4.x; hv[1] = t4.y; hv[2] = t4.z; hv[3] = t4.w;
        } else if constexpr (NB == 2) {
            float2 t2 = *(const float2*)&sHT[k * SP + ng * 2];
            hv[0] = t2.x; hv[1] = t2.y;
        } else {
            hv[0] = sHT[k * SP + ng];
        }
        float4 wr = *(const float4*)&sWr[k * OUT + o4 * 4];
        float4 wz = *(const float4*)&sWz[k * OUT + o4 * 4];
#pragma unroll
        for (int i = 0; i < NB; i++) {
            aR[i].x = fmaf(hv[i], wr.x, aR[i].x);
            aR[i].y = fmaf(hv[i], wr.y, aR[i].y);
            aR[i].z = fmaf(hv[i], wr.z, aR[i].z);
            aR[i].w = fmaf(hv[i], wr.w, aR[i].w);
            aZ[i].x = fmaf(hv[i], wz.x, aZ[i].x);
            aZ[i].y = fmaf(hv[i], wz.y, aZ[i].y);
            aZ[i].z = fmaf(hv[i], wz.z, aZ[i].z);
            aZ[i].w = fmaf(hv[i], wz.w, aZ[i].w);
        }
    }
#pragma unroll
    for (int i = 0; i < NB; i++) {
        int nn = n0 + i;
        if (nn < N) {
            ((float4*)y)[nn * O4 + o4] = aR[i];
            ((float4*)z)[nn * O4 + o4] = aZ[i];
        }
    }
}

__global__ void __launch_bounds__(256, 4) fused2_kernel(
    const float* __restrict__ lf,
    const float* __restrict__ Wr, const float* __restrict__ Wo,
    const float* __restrict__ b, int N)
{
    fused_layer<32, 16, 48, 4>(g_y1, g_z1, lf, Wr, Wo, b, g_y2, g_z2, N);
}

__global__ void __launch_bounds__(256, 4) fused3_kernel(
    const float* __restrict__ Wr, const float* __restrict__ Wo,
    const float* __restrict__ b, int N)
{
    fused_layer<48, 0, 16, 2>(g_y2, g_z2, nullptr, Wr, Wo, b, g_y3, g_z3, N);
}

// ---------------- final gather + epilogue: out = sum y3[src] + z3 + ax ---
__global__ void gather_final_kernel(const float* __restrict__ ax,
                                    float* __restrict__ out, int N)
{
    int t = blockIdx.x * blockDim.x + threadIdx.x;
    if (t >= N * 4) return;
    int n = t >> 2;
    int c = t & 3;
    int cnt = min(g_cnt[n], BK);
    const int* bk = &g_buck[n * BK];
    float4 acc = make_float4(0.f, 0.f, 0.f, 0.f);
    int j = 0;
    for (; j + 4 <= cnt; j += 4) {
        int s0 = __ldg(bk+j+0), s1 = __ldg(bk+j+1);
        int s2 = __ldg(bk+j+2), s3 = __ldg(bk+j+3);
        float4 v0 = __ldg((const float4*)g_y3 + (long)s0 * 4 + c);
        float4 v1 = __ldg((const float4*)g_y3 + (long)s1 * 4 + c);
        float4 v2 = __ldg((const float4*)g_y3 + (long)s2 * 4 + c);
        float4 v3 = __ldg((const float4*)g_y3 + (long)s3 * 4 + c);
        acc.x += (v0.x + v1.x) + (v2.x + v3.x);
        acc.y += (v0.y + v1.y) + (v2.y + v3.y);
        acc.z += (v0.z + v1.z) + (v2.z + v3.z);
        acc.w += (v0.w + v1.w) + (v2.w + v3.w);
    }
    for (; j < cnt; j++) {
        int s = __ldg(bk + j);
        float4 v = __ldg((const float4*)g_y3 + (long)s * 4 + c);
        acc.x += v.x; acc.y += v.y; acc.z += v.z; acc.w += v.w;
    }
    float4 zz = ((const float4*)g_z3)[t];
    float4 xx = __ldg((const float4*)ax + t);
    ((float4*)out)[t] = make_float4(acc.x + zz.x + xx.x,
                                    acc.y + zz.y + xx.y,
                                    acc.z + zz.z + xx.z,
                                    acc.w + zz.w + xx.w);
}

// ---------------- launch (serial; R10's fork-join reverted) --------------
extern "C" void kernel_launch(void* const* d_in, const int* in_sizes, int n_in,
                              void* d_out, int out_size)
{
    (void)n_in; (void)out_size;
    const float* x   = (const float*)d_in[0];
    const int*   ei  = (const int*)d_in[1];     // int32 (JAX x64 disabled)
    const float* ax  = (const float*)d_in[2];
    const float* lf  = (const float*)d_in[3];
    const float* W1r = (const float*)d_in[4];
    const float* b1  = (const float*)d_in[5];
    const float* W1o = (const float*)d_in[6];
    const float* W2r = (const float*)d_in[7];
    const float* b2  = (const float*)d_in[8];
    const float* W2o = (const float*)d_in[9];
    const float* W3r = (const float*)d_in[10];
    const float* b3  = (const float*)d_in[11];
    const float* W3o = (const float*)d_in[12];

    int N = in_sizes[0] / 48;
    int E = in_sizes[1] / 2;

    zero_cnt_kernel<<<CDIV(N, 256), 256>>>(N);
    bucket_kernel<<<CDIV(E, 256), 256>>>(ei, E, N);

    gemm1_kernel<<<CDIV(N, 128), 256>>>(x, ax, W1r, W1o, b1, N);
    fused2_kernel<<<CDIV(N, 64), 256>>>(lf, W2r, W2o, b2, N);
    fused3_kernel<<<CDIV(N, 64), 256>>>(W3r, W3o, b3, N);
    gather_final_kernel<<<CDIV(N * 4, 256), 256>>>(ax, (float*)d_out, N);
}

// round 13
// speedup vs baseline: 1.2278x; 1.0225x over previous
#include <cuda_runtime.h>

#define CDIV(a,b) (((a)+(b)-1)/(b))

typedef unsigned long long ull;

static const int MAXN = 100000;
static const int MAXE = 1600000;
static const int BK   = 64;      // bucket capacity; P(deg>64) ~ 1e-18

// ---------------- packed f32x2 helpers (sm_103a FFMA2) ----------------
__device__ __forceinline__ ull dup_f32x2(float v) {
    ull r;
    unsigned int u = __float_as_uint(v);
    asm("mov.b64 %0, {%1, %1};" : "=l"(r) : "r"(u));
    return r;
}
__device__ __forceinline__ void fma_f32x2(ull& d, ull a, ull b) {
    asm("fma.rn.f32x2 %0, %1, %2, %0;" : "+l"(d) : "l"(a), "l"(b));
}
__device__ __forceinline__ float2 unpack_f32x2(ull v) {
    unsigned int lo, hi;
    asm("mov.b64 {%0, %1}, %2;" : "=r"(lo), "=r"(hi) : "l"(v));
    return make_float2(__uint_as_float(lo), __uint_as_float(hi));
}

// ---------------- scratch (device globals; no allocation) ----------------
__device__ int g_cnt[MAXN];
__device__ int g_buck[MAXN * BK];

__device__ __align__(16) float g_y1[MAXN*32];
__device__ __align__(16) float g_z1[MAXN*32];
__device__ __align__(16) float g_y2[MAXN*48];
__device__ __align__(16) float g_z2[MAXN*48];
__device__ __align__(16) float g_y3[MAXN*16];
__device__ __align__(16) float g_z3[MAXN*16];

// ---------------- bucket build (scan-free CSR) ----------------
__global__ void zero_cnt_kernel(int N) {
    int t = blockIdx.x * blockDim.x + threadIdx.x;
    if (t < N) g_cnt[t] = 0;
}

__global__ void bucket_kernel(const int* __restrict__ ei, int E, int N) {
    int t = blockIdx.x * blockDim.x + threadIdx.x;
    if (t >= E) return;
    int s = min(max(ei[t], 0), N - 1);
    int d = min(max(ei[E + t], 0), N - 1);
    int p = atomicAdd(&g_cnt[d], 1);
    if (p < BK) g_buck[d * BK + p] = s;
}

// ---------------- layer 1 GEMM: y1 = h@W1rel, z1 = h@W1root + b1 --------
// k-outer, packed f32x2. OUT=32 -> O4=8 float4 groups; each og half owns
// FOUR groups (o4 = og*4 + oo, oo<4).  (R12 bug: wrote only 2 -> half the
// outputs stayed poisoned.)
__global__ void __launch_bounds__(256) gemm1_kernel(
    const float* __restrict__ x, const float* __restrict__ ax,
    const float* __restrict__ Wr, const float* __restrict__ Wo,
    const float* __restrict__ bias, int N)
{
    constexpr int IN = 64, OUT = 32;
    __shared__ float sWr[IN * OUT];
    __shared__ float sWz[IN * OUT];
    __shared__ float sB[OUT];
    int tid = threadIdx.x;
    for (int i = tid; i < IN * OUT; i += 256) {
        sWr[i] = Wr[i];
        sWz[i] = Wo[i];
    }
    if (tid < OUT) sB[tid] = bias[tid];
    __syncthreads();

    int n  = blockIdx.x * 128 + (tid & 127);
    int og = tid >> 7;          // warp-uniform output half
    if (n >= N) return;

    float h[IN];
#pragma unroll
    for (int c = 0; c < 12; c++) {
        float4 v = __ldg((const float4*)x + n * 12 + c);
        h[4*c+0] = v.x; h[4*c+1] = v.y; h[4*c+2] = v.z; h[4*c+3] = v.w;
    }
#pragma unroll
    for (int c = 0; c < 4; c++) {
        float4 v = __ldg((const float4*)ax + n * 4 + c);
        h[48+4*c+0] = v.x; h[48+4*c+1] = v.y;
        h[48+4*c+2] = v.z; h[48+4*c+3] = v.w;
    }

    // accumulators: 4 o4-groups x (lo,hi) pairs for both matrices
    ull aRlo[4], aRhi[4], aZlo[4], aZhi[4];
#pragma unroll
    for (int oo = 0; oo < 4; oo++) {
        int o4 = og * 4 + oo;
        aRlo[oo] = 0ull; aRhi[oo] = 0ull;
        aZlo[oo] = *(const ull*)&sB[o4 * 4];
        aZhi[oo] = *(const ull*)&sB[o4 * 4 + 2];
    }

#pragma unroll
    for (int k = 0; k < IN; k++) {
        ull hd = dup_f32x2(h[k]);
#pragma unroll
        for (int oo = 0; oo < 4; oo++) {
            int o4 = og * 4 + oo;
            ulonglong2 wr = *(const ulonglong2*)&sWr[k * OUT + o4 * 4];
            ulonglong2 wz = *(const ulonglong2*)&sWz[k * OUT + o4 * 4];
            fma_f32x2(aRlo[oo], hd, wr.x);
            fma_f32x2(aRhi[oo], hd, wr.y);
            fma_f32x2(aZlo[oo], hd, wz.x);
            fma_f32x2(aZhi[oo], hd, wz.y);
        }
    }

#pragma unroll
    for (int oo = 0; oo < 4; oo++) {
        int o4 = og * 4 + oo;
        float2 rl = unpack_f32x2(aRlo[oo]), rh = unpack_f32x2(aRhi[oo]);
        float2 zl = unpack_f32x2(aZlo[oo]), zh = unpack_f32x2(aZhi[oo]);
        ((float4*)g_y1)[n * 8 + o4] = make_float4(rl.x, rl.y, rh.x, rh.y);
        ((float4*)g_z1)[n * 8 + o4] = make_float4(zl.x, zl.y, zh.x, zh.y);
    }
}

// ---------------- fused layer: gather + relu + dual node-blocked GEMM ----
// Phase 1 (256 threads, 4/node): gather rows, relu(+z), write TRANSPOSED
//   h tile sHT[k][node].
// Phase 2 (NG*O4 threads): thread = (node-group of NB, o4); covers ALL O4
//   groups. Packed f32x2 FMAs: weights viewed as ulonglong2 (free), h
//   duplicated once per (k, node), shared by 8 MACs across both matrices.
template<int INA, int INB, int OUT, int NB>
__device__ __forceinline__ void fused_layer(
    const float* __restrict__ yprev, const float* __restrict__ zprev,
    const float* __restrict__ B,
    const float* __restrict__ Wr, const float* __restrict__ Wo,
    const float* __restrict__ bias,
    float* __restrict__ y, float* __restrict__ z, int N)
{
    constexpr int TPN = 4;
    constexpr int NPB = 64;                 // nodes per block
    constexpr int IN  = INA + INB;
    constexpr int A4  = INA / 4;            // gathered float4 chunks
    constexpr int CPT = A4 / TPN;           // chunks per sub-thread
    constexpr int B4  = INB / 4;            // extra-input chunks
    constexpr int O4  = OUT / 4;
    constexpr int SP  = 68;                 // sHT row stride (floats), %4==0
    constexpr int NG  = NPB / NB;           // node groups
    constexpr int NT  = NG * O4;            // GEMM threads
    static_assert(NT <= 256, "GEMM thread count");

    __shared__ float sWr[IN * OUT];
    __shared__ float sWz[IN * OUT];
    __shared__ float sB[OUT];
    __shared__ __align__(16) float sHT[IN * SP];

    int tid = threadIdx.x;
    for (int i = tid; i < IN * OUT; i += 256) {
        sWr[i] = Wr[i];
        sWz[i] = Wo[i];
    }
    if (tid < OUT) sB[tid] = bias[tid];

    // ---- phase 1: gather ----
    int nl  = tid / TPN;
    int sub = tid % TPN;
    int n   = blockIdx.x * NPB + nl;

    if (n < N) {
        float4 acc[CPT];
#pragma unroll
        for (int c = 0; c < CPT; c++) acc[c] = make_float4(0.f, 0.f, 0.f, 0.f);

        int cnt = min(g_cnt[n], BK);
        const int* bk = &g_buck[n * BK];
        const float4* yp = (const float4*)yprev;
        for (int j = 0; j < cnt; j++) {
            int s = __ldg(bk + j);
#pragma unroll
            for (int c = 0; c < CPT; c++) {
                float4 v = __ldg(yp + (long)s * A4 + sub * CPT + c);
                acc[c].x += v.x; acc[c].y += v.y;
                acc[c].z += v.z; acc[c].w += v.w;
            }
        }
#pragma unroll
        for (int c = 0; c < CPT; c++) {
            int ch = sub * CPT + c;
            float4 zz = ((const float4*)zprev)[n * A4 + ch];
            int kb = ch * 4;
            sHT[(kb+0) * SP + nl] = fmaxf(acc[c].x + zz.x, 0.f);
            sHT[(kb+1) * SP + nl] = fmaxf(acc[c].y + zz.y, 0.f);
            sHT[(kb+2) * SP + nl] = fmaxf(acc[c].z + zz.z, 0.f);
            sHT[(kb+3) * SP + nl] = fmaxf(acc[c].w + zz.w, 0.f);
        }
        if constexpr (B4 > 0) {
            static_assert(B4 == TPN || B4 == 0, "B4 must equal TPN");
            float4 v = __ldg((const float4*)B + n * B4 + sub);
            int kb = INA + sub * 4;
            sHT[(kb+0) * SP + nl] = v.x;
            sHT[(kb+1) * SP + nl] = v.y;
            sHT[(kb+2) * SP + nl] = v.z;
            sHT[(kb+3) * SP + nl] = v.w;
        }
    }
    __syncthreads();

    // ---- phase 2: node-blocked dual GEMM, packed f32x2 ----
    if (tid >= NT) return;
    int o4 = tid % O4;
    int ng = tid / O4;
    int n0 = blockIdx.x * NPB + ng * NB;

    ull aRlo[NB], aRhi[NB], aZlo[NB], aZhi[NB];
    ull blo = *(const ull*)&sB[o4 * 4];
    ull bhi = *(const ull*)&sB[o4 * 4 + 2];
#pragma unroll
    for (int i = 0; i < NB; i++) {
        aRlo[i] = 0ull; aRhi[i] = 0ull;
        aZlo[i] = blo;  aZhi[i] = bhi;
    }

#pragma unroll
    for (int k = 0; k < IN; k++) {
        float hv[NB];
        if constexpr (NB == 4) {
            float4 t4 = *(const float4*)&sHT[k * SP + ng * 4];
            hv[0] = t4.x; hv[1] = t4.y; hv[2] = t4.z; hv[3] = t4.w;
        } else if constexpr (NB == 2) {
            float2 t2 = *(const float2*)&sHT[k * SP + ng * 2];
            hv[0] = t2.x; hv[1] = t2.y;
        } else {
            hv[0] = sHT[k * SP + ng];
        }
        ulonglong2 wr = *(const ulonglong2*)&sWr[k * OUT + o4 * 4];
        ulonglong2 wz = *(const ulonglong2*)&sWz[k * OUT + o4 * 4];
#pragma unroll
        for (int i = 0; i < NB; i++) {
            ull hd = dup_f32x2(hv[i]);
            fma_f32x2(aRlo[i], hd, wr.x);
            fma_f32x2(aRhi[i], hd, wr.y);
            fma_f32x2(aZlo[i], hd, wz.x);
            fma_f32x2(aZhi[i], hd, wz.y);
        }
    }
#pragma unroll
    for (int i = 0; i < NB; i++) {
        int nn = n0 + i;
        if (nn < N) {
            float2 rl = unpack_f32x2(aRlo[i]), rh = unpack_f32x2(aRhi[i]);
            float2 zl = unpack_f32x2(aZlo[i]), zh = unpack_f32x2(aZhi[i]);
            ((float4*)y)[nn * O4 + o4] = make_float4(rl.x, rl.y, rh.x, rh.y);
            ((float4*)z)[nn * O4 + o4] = make_float4(zl.x, zl.y, zh.x, zh.y);
        }
    }
}

__global__ void __launch_bounds__(256, 4) fused2_kernel(
    const float* __restrict__ lf,
    const float* __restrict__ Wr, const float* __restrict__ Wo,
    const float* __restrict__ b, int N)
{
    fused_layer<32, 16, 48, 4>(g_y1, g_z1, lf, Wr, Wo, b, g_y2, g_z2, N);
}

__global__ void __launch_bounds__(256, 4) fused3_kernel(
    const float* __restrict__ Wr, const float* __restrict__ Wo,
    const float* __restrict__ b, int N)
{
    fused_layer<48, 0, 16, 2>(g_y2, g_z2, nullptr, Wr, Wo, b, g_y3, g_z3, N);
}

// ---------------- final gather + epilogue: out = sum y3[src] + z3 + ax ---
__global__ void gather_final_kernel(const float* __restrict__ ax,
                                    float* __restrict__ out, int N)
{
    int t = blockIdx.x * blockDim.x + threadIdx.x;
    if (t >= N * 4) return;
    int n = t >> 2;
    int c = t & 3;
    int cnt = min(g_cnt[n], BK);
    const int* bk = &g_buck[n * BK];
    float4 acc = make_float4(0.f, 0.f, 0.f, 0.f);
    int j = 0;
    for (; j + 4 <= cnt; j += 4) {
        int s0 = __ldg(bk+j+0), s1 = __ldg(bk+j+1);
        int s2 = __ldg(bk+j+2), s3 = __ldg(bk+j+3);
        float4 v0 = __ldg((const float4*)g_y3 + (long)s0 * 4 + c);
        float4 v1 = __ldg((const float4*)g_y3 + (long)s1 * 4 + c);
        float4 v2 = __ldg((const float4*)g_y3 + (long)s2 * 4 + c);
        float4 v3 = __ldg((const float4*)g_y3 + (long)s3 * 4 + c);
        acc.x += (v0.x + v1.x) + (v2.x + v3.x);
        acc.y += (v0.y + v1.y) + (v2.y + v3.y);
        acc.z += (v0.z + v1.z) + (v2.z + v3.z);
        acc.w += (v0.w + v1.w) + (v2.w + v3.w);
    }
    for (; j < cnt; j++) {
        int s = __ldg(bk + j);
        float4 v = __ldg((const float4*)g_y3 + (long)s * 4 + c);
        acc.x += v.x; acc.y += v.y; acc.z += v.z; acc.w += v.w;
    }
    float4 zz = ((const float4*)g_z3)[t];
    float4 xx = __ldg((const float4*)ax + t);
    ((float4*)out)[t] = make_float4(acc.x + zz.x + xx.x,
                                    acc.y + zz.y + xx.y,
                                    acc.z + zz.z + xx.z,
                                    acc.w + zz.w + xx.w);
}

// ---------------- launch (serial) ----------------
extern "C" void kernel_launch(void* const* d_in, const int* in_sizes, int n_in,
                              void* d_out, int out_size)
{
    (void)n_in; (void)out_size;
    const float* x   = (const float*)d_in[0];
    const int*   ei  = (const int*)d_in[1];     // int32 (JAX x64 disabled)
    const float* ax  = (const float*)d_in[2];
    const float* lf  = (const float*)d_in[3];
    const float* W1r = (const float*)d_in[4];
    const float* b1  = (const float*)d_in[5];
    const float* W1o = (const float*)d_in[6];
    const float* W2r = (const float*)d_in[7];
    const float* b2  = (const float*)d_in[8];
    const float* W2o = (const float*)d_in[9];
    const float* W3r = (const float*)d_in[10];
    const float* b3  = (const float*)d_in[11];
    const float* W3o = (const float*)d_in[12];

    int N = in_sizes[0] / 48;
    int E = in_sizes[1] / 2;

    zero_cnt_kernel<<<CDIV(N, 256), 256>>>(N);
    bucket_kernel<<<CDIV(E, 256), 256>>>(ei, E, N);

    gemm1_kernel<<<CDIV(N, 128), 256>>>(x, ax, W1r, W1o, b1, N);
    fused2_kernel<<<CDIV(N, 64), 256>>>(lf, W2r, W2o, b2, N);
    fused3_kernel<<<CDIV(N, 64), 256>>>(W3r, W3o, b3, N);
    gather_final_kernel<<<CDIV(N * 4, 256), 256>>>(ax, (float*)d_out, N);
}

// round 14
// speedup vs baseline: 1.2710x; 1.0352x over previous
#include <cuda_runtime.h>

#define CDIV(a,b) (((a)+(b)-1)/(b))

typedef unsigned long long ull;

static const int MAXN = 100000;
static const int MAXE = 1600000;
static const int BK   = 64;      // bucket capacity; P(deg>64) ~ 1e-18

// ---------------- packed f32x2 helpers (sm_103a FFMA2) ----------------
__device__ __forceinline__ ull dup_f32x2(float v) {
    ull r;
    unsigned int u = __float_as_uint(v);
    asm("mov.b64 %0, {%1, %1};" : "=l"(r) : "r"(u));
    return r;
}
__device__ __forceinline__ void fma_f32x2(ull& d, ull a, ull b) {
    asm("fma.rn.f32x2 %0, %1, %2, %0;" : "+l"(d) : "l"(a), "l"(b));
}
__device__ __forceinline__ float2 unpack_f32x2(ull v) {
    unsigned int lo, hi;
    asm("mov.b64 {%0, %1}, %2;" : "=r"(lo), "=r"(hi) : "l"(v));
    return make_float2(__uint_as_float(lo), __uint_as_float(hi));
}

// ---------------- scratch (device globals; no allocation) ----------------
__device__ int g_cnt[MAXN];
__device__ int g_buck[MAXN * BK];

__device__ __align__(16) float g_y1[MAXN*32];
__device__ __align__(16) float g_z1[MAXN*32];
__device__ __align__(16) float g_y2[MAXN*48];
__device__ __align__(16) float g_z2[MAXN*48];
__device__ __align__(16) float g_y3[MAXN*16];
__device__ __align__(16) float g_z3[MAXN*16];

// ---------------- zero counters (must precede bucket atomics) -----------
__global__ void zero_cnt_kernel(int N) {
    int t = blockIdx.x * blockDim.x + threadIdx.x;
    if (t < N) g_cnt[t] = 0;
}

// ---------------- combined gemm1 + bucket build -------------------------
// Blocks [0, nGemm): layer-1 dual GEMM (FMA-bound).
// Blocks [nGemm, ..): bucket build (LTS-atomic-bound).
// Complementary pipe usage -> the SM scheduler overlaps them inside one
// kernel; no stream/event machinery in the captured graph.
__device__ __forceinline__ void gemm1_body(
    const float* __restrict__ x, const float* __restrict__ ax,
    const float* __restrict__ Wr, const float* __restrict__ Wo,
    const float* __restrict__ bias, int N, int bid)
{
    constexpr int IN = 64, OUT = 32;
    __shared__ float sWr[IN * OUT];
    __shared__ float sWz[IN * OUT];
    __shared__ float sB[OUT];
    int tid = threadIdx.x;
    for (int i = tid; i < IN * OUT; i += 256) {
        sWr[i] = Wr[i];
        sWz[i] = Wo[i];
    }
    if (tid < OUT) sB[tid] = bias[tid];
    __syncthreads();

    int n  = bid * 128 + (tid & 127);
    int og = tid >> 7;          // warp-uniform output half
    if (n >= N) return;

    float h[IN];
#pragma unroll
    for (int c = 0; c < 12; c++) {
        float4 v = __ldg((const float4*)x + n * 12 + c);
        h[4*c+0] = v.x; h[4*c+1] = v.y; h[4*c+2] = v.z; h[4*c+3] = v.w;
    }
#pragma unroll
    for (int c = 0; c < 4; c++) {
        float4 v = __ldg((const float4*)ax + n * 4 + c);
        h[48+4*c+0] = v.x; h[48+4*c+1] = v.y;
        h[48+4*c+2] = v.z; h[48+4*c+3] = v.w;
    }

    ull aRlo[4], aRhi[4], aZlo[4], aZhi[4];
#pragma unroll
    for (int oo = 0; oo < 4; oo++) {
        int o4 = og * 4 + oo;
        aRlo[oo] = 0ull; aRhi[oo] = 0ull;
        aZlo[oo] = *(const ull*)&sB[o4 * 4];
        aZhi[oo] = *(const ull*)&sB[o4 * 4 + 2];
    }

#pragma unroll
    for (int k = 0; k < IN; k++) {
        ull hd = dup_f32x2(h[k]);
#pragma unroll
        for (int oo = 0; oo < 4; oo++) {
            int o4 = og * 4 + oo;
            ulonglong2 wr = *(const ulonglong2*)&sWr[k * OUT + o4 * 4];
            ulonglong2 wz = *(const ulonglong2*)&sWz[k * OUT + o4 * 4];
            fma_f32x2(aRlo[oo], hd, wr.x);
            fma_f32x2(aRhi[oo], hd, wr.y);
            fma_f32x2(aZlo[oo], hd, wz.x);
            fma_f32x2(aZhi[oo], hd, wz.y);
        }
    }

#pragma unroll
    for (int oo = 0; oo < 4; oo++) {
        int o4 = og * 4 + oo;
        float2 rl = unpack_f32x2(aRlo[oo]), rh = unpack_f32x2(aRhi[oo]);
        float2 zl = unpack_f32x2(aZlo[oo]), zh = unpack_f32x2(aZhi[oo]);
        ((float4*)g_y1)[n * 8 + o4] = make_float4(rl.x, rl.y, rh.x, rh.y);
        ((float4*)g_z1)[n * 8 + o4] = make_float4(zl.x, zl.y, zh.x, zh.y);
    }
}

__device__ __forceinline__ void bucket_body(
    const int* __restrict__ ei, int E, int N, int bid)
{
    int t = bid * 256 + threadIdx.x;
    if (t >= E) return;
    int s = min(max(ei[t], 0), N - 1);
    int d = min(max(ei[E + t], 0), N - 1);
    int p = atomicAdd(&g_cnt[d], 1);
    if (p < BK) g_buck[d * BK + p] = s;
}

__global__ void __launch_bounds__(256) gemm1_bucket_kernel(
    const float* __restrict__ x, const float* __restrict__ ax,
    const float* __restrict__ Wr, const float* __restrict__ Wo,
    const float* __restrict__ bias,
    const int* __restrict__ ei, int E, int N, int nGemm)
{
    if ((int)blockIdx.x < nGemm)
        gemm1_body(x, ax, Wr, Wo, bias, N, blockIdx.x);
    else
        bucket_body(ei, E, N, blockIdx.x - nGemm);
}

// ---------------- fused layer: gather + relu + dual node-blocked GEMM ----
// Phase 1 (256 threads, 4/node): gather rows, relu(+z), write TRANSPOSED
//   h tile sHT[k][node].
// Phase 2 (NG*O4 threads): thread = (node-group of NB, o4). Packed f32x2
//   FMAs: weights viewed as ulonglong2, h duplicated once per (k, node).
template<int INA, int INB, int OUT, int NB>
__device__ __forceinline__ void fused_layer(
    const float* __restrict__ yprev, const float* __restrict__ zprev,
    const float* __restrict__ B,
    const float* __restrict__ Wr, const float* __restrict__ Wo,
    const float* __restrict__ bias,
    float* __restrict__ y, float* __restrict__ z, int N)
{
    constexpr int TPN = 4;
    constexpr int NPB = 64;                 // nodes per block
    constexpr int IN  = INA + INB;
    constexpr int A4  = INA / 4;            // gathered float4 chunks
    constexpr int CPT = A4 / TPN;           // chunks per sub-thread
    constexpr int B4  = INB / 4;            // extra-input chunks
    constexpr int O4  = OUT / 4;
    constexpr int SP  = 68;                 // sHT row stride (floats), %4==0
    constexpr int NG  = NPB / NB;           // node groups
    constexpr int NT  = NG * O4;            // GEMM threads
    static_assert(NT <= 256, "GEMM thread count");

    __shared__ float sWr[IN * OUT];
    __shared__ float sWz[IN * OUT];
    __shared__ float sB[OUT];
    __shared__ __align__(16) float sHT[IN * SP];

    int tid = threadIdx.x;
    for (int i = tid; i < IN * OUT; i += 256) {
        sWr[i] = Wr[i];
        sWz[i] = Wo[i];
    }
    if (tid < OUT) sB[tid] = bias[tid];

    // ---- phase 1: gather ----
    int nl  = tid / TPN;
    int sub = tid % TPN;
    int n   = blockIdx.x * NPB + nl;

    if (n < N) {
        float4 acc[CPT];
#pragma unroll
        for (int c = 0; c < CPT; c++) acc[c] = make_float4(0.f, 0.f, 0.f, 0.f);

        int cnt = min(g_cnt[n], BK);
        const int* bk = &g_buck[n * BK];
        const float4* yp = (const float4*)yprev;
        for (int j = 0; j < cnt; j++) {
            int s = __ldg(bk + j);
#pragma unroll
            for (int c = 0; c < CPT; c++) {
                float4 v = __ldg(yp + (long)s * A4 + sub * CPT + c);
                acc[c].x += v.x; acc[c].y += v.y;
                acc[c].z += v.z; acc[c].w += v.w;
            }
        }
#pragma unroll
        for (int c = 0; c < CPT; c++) {
            int ch = sub * CPT + c;
            float4 zz = ((const float4*)zprev)[n * A4 + ch];
            int kb = ch * 4;
            sHT[(kb+0) * SP + nl] = fmaxf(acc[c].x + zz.x, 0.f);
            sHT[(kb+1) * SP + nl] = fmaxf(acc[c].y + zz.y, 0.f);
            sHT[(kb+2) * SP + nl] = fmaxf(acc[c].z + zz.z, 0.f);
            sHT[(kb+3) * SP + nl] = fmaxf(acc[c].w + zz.w, 0.f);
        }
        if constexpr (B4 > 0) {
            static_assert(B4 == TPN || B4 == 0, "B4 must equal TPN");
            float4 v = __ldg((const float4*)B + n * B4 + sub);
            int kb = INA + sub * 4;
            sHT[(kb+0) * SP + nl] = v.x;
            sHT[(kb+1) * SP + nl] = v.y;
            sHT[(kb+2) * SP + nl] = v.z;
            sHT[(kb+3) * SP + nl] = v.w;
        }
    }
    __syncthreads();

    // ---- phase 2: node-blocked dual GEMM, packed f32x2 ----
    if (tid >= NT) return;
    int o4 = tid % O4;
    int ng = tid / O4;
    int n0 = blockIdx.x * NPB + ng * NB;

    ull aRlo[NB], aRhi[NB], aZlo[NB], aZhi[NB];
    ull blo = *(const ull*)&sB[o4 * 4];
    ull bhi = *(const ull*)&sB[o4 * 4 + 2];
#pragma unroll
    for (int i = 0; i < NB; i++) {
        aRlo[i] = 0ull; aRhi[i] = 0ull;
        aZlo[i] = blo;  aZhi[i] = bhi;
    }

#pragma unroll
    for (int k = 0; k < IN; k++) {
        float hv[NB];
        if constexpr (NB == 4) {
            float4 t4 = *(const float4*)&sHT[k * SP + ng * 4];
            hv[0] = t4.x; hv[1] = t4.y; hv[2] = t4.z; hv[3] = t4.w;
        } else if constexpr (NB == 2) {
            float2 t2 = *(const float2*)&sHT[k * SP + ng * 2];
            hv[0] = t2.x; hv[1] = t2.y;
        } else {
            hv[0] = sHT[k * SP + ng];
        }
        ulonglong2 wr = *(const ulonglong2*)&sWr[k * OUT + o4 * 4];
        ulonglong2 wz = *(const ulonglong2*)&sWz[k * OUT + o4 * 4];
#pragma unroll
        for (int i = 0; i < NB; i++) {
            ull hd = dup_f32x2(hv[i]);
            fma_f32x2(aRlo[i], hd, wr.x);
            fma_f32x2(aRhi[i], hd, wr.y);
            fma_f32x2(aZlo[i], hd, wz.x);
            fma_f32x2(aZhi[i], hd, wz.y);
        }
    }
#pragma unroll
    for (int i = 0; i < NB; i++) {
        int nn = n0 + i;
        if (nn < N) {
            float2 rl = unpack_f32x2(aRlo[i]), rh = unpack_f32x2(aRhi[i]);
            float2 zl = unpack_f32x2(aZlo[i]), zh = unpack_f32x2(aZhi[i]);
            ((float4*)y)[nn * O4 + o4] = make_float4(rl.x, rl.y, rh.x, rh.y);
            ((float4*)z)[nn * O4 + o4] = make_float4(zl.x, zl.y, zh.x, zh.y);
        }
    }
}

__global__ void __launch_bounds__(256, 4) fused2_kernel(
    const float* __restrict__ lf,
    const float* __restrict__ Wr, const float* __restrict__ Wo,
    const float* __restrict__ b, int N)
{
    fused_layer<32, 16, 48, 4>(g_y1, g_z1, lf, Wr, Wo, b, g_y2, g_z2, N);
}

__global__ void __launch_bounds__(256, 4) fused3_kernel(
    const float* __restrict__ Wr, const float* __restrict__ Wo,
    const float* __restrict__ b, int N)
{
    fused_layer<48, 0, 16, 2>(g_y2, g_z2, nullptr, Wr, Wo, b, g_y3, g_z3, N);
}

// ---------------- final gather + epilogue: out = sum y3[src] + z3 + ax ---
__global__ void gather_final_kernel(const float* __restrict__ ax,
                                    float* __restrict__ out, int N)
{
    int t = blockIdx.x * blockDim.x + threadIdx.x;
    if (t >= N * 4) return;
    int n = t >> 2;
    int c = t & 3;
    int cnt = min(g_cnt[n], BK);
    const int* bk = &g_buck[n * BK];
    float4 acc = make_float4(0.f, 0.f, 0.f, 0.f);
    int j = 0;
    for (; j + 4 <= cnt; j += 4) {
        int s0 = __ldg(bk+j+0), s1 = __ldg(bk+j+1);
        int s2 = __ldg(bk+j+2), s3 = __ldg(bk+j+3);
        float4 v0 = __ldg((const float4*)g_y3 + (long)s0 * 4 + c);
        float4 v1 = __ldg((const float4*)g_y3 + (long)s1 * 4 + c);
        float4 v2 = __ldg((const float4*)g_y3 + (long)s2 * 4 + c);
        float4 v3 = __ldg((const float4*)g_y3 + (long)s3 * 4 + c);
        acc.x += (v0.x + v1.x) + (v2.x + v3.x);
        acc.y += (v0.y + v1.y) + (v2.y + v3.y);
        acc.z += (v0.z + v1.z) + (v2.z + v3.z);
        acc.w += (v0.w + v1.w) + (v2.w + v3.w);
    }
    for (; j < cnt; j++) {
        int s = __ldg(bk + j);
        float4 v = __ldg((const float4*)g_y3 + (long)s * 4 + c);
        acc.x += v.x; acc.y += v.y; acc.z += v.z; acc.w += v.w;
    }
    float4 zz = ((const float4*)g_z3)[t];
    float4 xx = __ldg((const float4*)ax + t);
    ((float4*)out)[t] = make_float4(acc.x + zz.x + xx.x,
                                    acc.y + zz.y + xx.y,
                                    acc.z + zz.z + xx.z,
                                    acc.w + zz.w + xx.w);
}

// ---------------- launch ----------------
extern "C" void kernel_launch(void* const* d_in, const int* in_sizes, int n_in,
                              void* d_out, int out_size)
{
    (void)n_in; (void)out_size;
    const float* x   = (const float*)d_in[0];
    const int*   ei  = (const int*)d_in[1];     // int32 (JAX x64 disabled)
    const float* ax  = (const float*)d_in[2];
    const float* lf  = (const float*)d_in[3];
    const float* W1r = (const float*)d_in[4];
    const float* b1  = (const float*)d_in[5];
    const float* W1o = (const float*)d_in[6];
    const float* W2r = (const float*)d_in[7];
    const float* b2  = (const float*)d_in[8];
    const float* W2o = (const float*)d_in[9];
    const float* W3r = (const float*)d_in[10];
    const float* b3  = (const float*)d_in[11];
    const float* W3o = (const float*)d_in[12];

    int N = in_sizes[0] / 48;
    int E = in_sizes[1] / 2;

    int nGemm   = CDIV(N, 128);
    int nBucket = CDIV(E, 256);

    zero_cnt_kernel<<<CDIV(N, 256), 256>>>(N);
    gemm1_bucket_kernel<<<nGemm + nBucket, 256>>>(
        x, ax, W1r, W1o, b1, ei, E, N, nGemm);

    fused2_kernel<<<CDIV(N, 64), 256>>>(lf, W2r, W2o, b2, N);
    fused3_kernel<<<CDIV(N, 64), 256>>>(W3r, W3o, b3, N);
    gather_final_kernel<<<CDIV(N * 4, 256), 256>>>(ax, (float*)d_out, N);
}